// round 2
// baseline (speedup 1.0000x reference)
#include <cuda_runtime.h>
#include <math.h>

#define R 40000
#define EMAX 500000
#define DH 64
#define NBIN 10
#define HN 8

// ---------------- scratch (static device globals; no runtime alloc) ----------
__device__ float g_emb  [R*DH];
__device__ float g_ahead[R*DH];
__device__ float g_atail[R*DH];
__device__ float g_wtail[R*DH];
__device__ float g_res  [R*DH];
__device__ int   g_deg  [R];
__device__ int   g_off  [R+1];
__device__ int   g_cursor[R];
__device__ int   g_etb  [EMAX];   // packed: tail | (bin<<20)

__device__ __forceinline__ float lk(float x) { return x > 0.f ? x : 0.2f * x; }

// ---------------- CSR build ----------------
__global__ void zero_deg_kernel() {
    int i = blockIdx.x * blockDim.x + threadIdx.x;
    if (i < R) g_deg[i] = 0;
}

__global__ void hist_kernel(const int* __restrict__ trip, int E) {
    int e = blockIdx.x * blockDim.x + threadIdx.x;
    if (e < E) {
        int h = trip[e * 3];
        h = min(max(h, 0), R - 1);
        atomicAdd(&g_deg[h], 1);
    }
}

__global__ void scan_kernel() {
    __shared__ int wsum[32];
    int t = threadIdx.x;
    int lane = t & 31, wid = t >> 5;
    if (t == 0) g_off[0] = 0;
    int carry = 0;
    for (int base = 0; base < R; base += 1024) {
        int idx = base + t;
        int v = (idx < R) ? g_deg[idx] : 0;
        int iv = v;
        #pragma unroll
        for (int o = 1; o < 32; o <<= 1) {
            int n = __shfl_up_sync(0xffffffffu, iv, o);
            if (lane >= o) iv += n;
        }
        if (lane == 31) wsum[wid] = iv;
        __syncthreads();
        if (wid == 0) {
            int ws = wsum[lane];
            #pragma unroll
            for (int o = 1; o < 32; o <<= 1) {
                int n = __shfl_up_sync(0xffffffffu, ws, o);
                if (lane >= o) ws += n;
            }
            wsum[lane] = ws;
        }
        __syncthreads();
        int prev = (wid > 0) ? wsum[wid - 1] : 0;
        int inc = carry + prev + iv;
        if (idx < R) { g_off[idx + 1] = inc; g_cursor[idx] = inc - v; }
        int total = wsum[31];
        __syncthreads();
        carry += total;
    }
}

__global__ void scatter_kernel(const int* __restrict__ trip, int E) {
    int e = blockIdx.x * blockDim.x + threadIdx.x;
    if (e < E) {
        int h = trip[e * 3];
        int t = trip[e * 3 + 1];
        int b = trip[e * 3 + 2];
        h = min(max(h, 0), R - 1);
        t = min(max(t, 0), R - 1);
        b = min(max(b, 0), NBIN - 1);
        int p = atomicAdd(&g_cursor[h], 1);
        g_etb[p] = t | (b << 20);
    }
}

// ---------------- GEMM: Y[R,64] = act(X[R,64] @ W[64,64] + bias) -------------
// block: 256 threads, 64 rows/block. thread = 4 rows x 4 cols.
// outsel: 0=g_emb 1=g_ahead 2=g_atail 3=g_wtail 4=g_res
__global__ void gemm_kernel(const float* X, const float* __restrict__ W,
                            const float* __restrict__ bias, int outsel, int act) {
    __shared__ float sW[64 * 64];
    __shared__ float sX[64 * 65];   // padded rows
    const float* Xp = X ? X : g_emb;
    float* Y = (outsel == 0) ? g_emb :
               (outsel == 1) ? g_ahead :
               (outsel == 2) ? g_atail :
               (outsel == 3) ? g_wtail : g_res;

    int t = threadIdx.x;
    const float* Xb = Xp + (size_t)blockIdx.x * 4096;
    #pragma unroll
    for (int i = 0; i < 16; i++) {
        int idx = t + i * 256;
        sW[idx] = W[idx];
        sX[(idx >> 6) * 65 + (idx & 63)] = Xb[idx];
    }
    __syncthreads();

    int cg = (t & 15) * 4;      // col base
    int rbase = (t >> 4) * 4;   // row base
    float4 a0 = {0,0,0,0}, a1 = a0, a2 = a0, a3 = a0;
    const float* x0 = &sX[rbase * 65];
    #pragma unroll
    for (int k = 0; k < 64; k++) {
        float4 w = *(const float4*)&sW[k * 64 + cg];
        float xv0 = x0[k], xv1 = x0[65 + k], xv2 = x0[130 + k], xv3 = x0[195 + k];
        a0.x += xv0 * w.x; a0.y += xv0 * w.y; a0.z += xv0 * w.z; a0.w += xv0 * w.w;
        a1.x += xv1 * w.x; a1.y += xv1 * w.y; a1.z += xv1 * w.z; a1.w += xv1 * w.w;
        a2.x += xv2 * w.x; a2.y += xv2 * w.y; a2.z += xv2 * w.z; a2.w += xv2 * w.w;
        a3.x += xv3 * w.x; a3.y += xv3 * w.y; a3.z += xv3 * w.z; a3.w += xv3 * w.w;
    }
    float4 b4 = {0,0,0,0};
    if (bias) b4 = *(const float4*)&bias[cg];
    a0.x += b4.x; a0.y += b4.y; a0.z += b4.z; a0.w += b4.w;
    a1.x += b4.x; a1.y += b4.y; a1.z += b4.z; a1.w += b4.w;
    a2.x += b4.x; a2.y += b4.y; a2.z += b4.z; a2.w += b4.w;
    a3.x += b4.x; a3.y += b4.y; a3.z += b4.z; a3.w += b4.w;
    if (act) {
        a0.x = fmaxf(a0.x, 0.f); a0.y = fmaxf(a0.y, 0.f); a0.z = fmaxf(a0.z, 0.f); a0.w = fmaxf(a0.w, 0.f);
        a1.x = fmaxf(a1.x, 0.f); a1.y = fmaxf(a1.y, 0.f); a1.z = fmaxf(a1.z, 0.f); a1.w = fmaxf(a1.w, 0.f);
        a2.x = fmaxf(a2.x, 0.f); a2.y = fmaxf(a2.y, 0.f); a2.z = fmaxf(a2.z, 0.f); a2.w = fmaxf(a2.w, 0.f);
        a3.x = fmaxf(a3.x, 0.f); a3.y = fmaxf(a3.y, 0.f); a3.z = fmaxf(a3.z, 0.f); a3.w = fmaxf(a3.w, 0.f);
    }
    int row = blockIdx.x * 64 + rbase;
    *(float4*)&Y[(row + 0) * 64 + cg] = a0;
    *(float4*)&Y[(row + 1) * 64 + cg] = a1;
    *(float4*)&Y[(row + 2) * 64 + cg] = a2;
    *(float4*)&Y[(row + 3) * 64 + cg] = a3;
}

// ---------------- attention: one warp per node, online softmax --------------
// outp == nullptr -> write g_emb, else write outp (final layer -> d_out)
__global__ void attn_kernel(const float* __restrict__ abin,
                            const float* __restrict__ avec,
                            float* outp) {
    __shared__ float s_abin[NBIN * HN];
    int t = threadIdx.x;
    if (t < NBIN * HN) s_abin[t] = lk(abin[t]);
    __syncthreads();

    int warp = t >> 5, lane = t & 31;
    int r = blockIdx.x * 8 + warp;
    if (r >= R) return;

    int h = lane >> 2;
    float2 ahv = ((const float2*)g_ahead)[r * 32 + lane];
    float avx = avec[h * 8 + (lane & 3) * 2];
    float avy = avec[h * 8 + (lane & 3) * 2 + 1];

    float m = -INFINITY, s = 0.f, a0 = 0.f, a1 = 0.f;
    int i = g_off[r], end = g_off[r + 1];
    for (; i < end; i++) {
        int etb = g_etb[i];
        int tt = etb & 0xFFFFF;
        int b  = etb >> 20;
        float2 at = ((const float2*)g_atail)[tt * 32 + lane];
        float2 wt = ((const float2*)g_wtail)[tt * 32 + lane];
        float z0 = lk(ahv.x + at.x);
        float z1 = lk(ahv.y + at.y);
        float p = z0 * avx + z1 * avy;
        p += __shfl_xor_sync(0xffffffffu, p, 1);
        p += __shfl_xor_sync(0xffffffffu, p, 2);
        float raw = p + s_abin[b * 8 + h];
        float mn = fmaxf(m, raw);
        float sc = __expf(m - mn);    // 0 on first edge (m=-inf), 1 if no new max
        float e  = __expf(raw - mn);
        s  = s  * sc + e;
        a0 = a0 * sc + e * wt.x;
        a1 = a1 * sc + e * wt.y;
        m = mn;
    }
    float inv = 1.f / (s + 1e-16f);
    float o0 = fmaxf(a0 * inv, 0.f);
    float o1 = fmaxf(a1 * inv, 0.f);
    float2 rv = ((const float2*)g_res)[r * 32 + lane];
    float2 ov;
    ov.x = o0 + rv.x;
    ov.y = o1 + rv.y;
    float* Y = outp ? outp : g_emb;
    ((float2*)Y)[r * 32 + lane] = ov;
}

// ---------------- host ----------------
extern "C" void kernel_launch(void* const* d_in, const int* in_sizes, int n_in,
                              void* d_out, int out_size) {
    const int*   trip     = (const int*)d_in[0];     // int32 (JAX x64 disabled)
    const float* rel_emb  = (const float*)d_in[1];
    const float* p1w      = (const float*)d_in[2];
    const float* p1b      = (const float*)d_in[3];
    const float* apw      = (const float*)d_in[4];   // (2,128,64)
    const float* apb      = (const float*)d_in[5];   // (2,64)
    const float* abin     = (const float*)d_in[6];   // (2,10,8,1)
    const float* avec     = (const float*)d_in[7];   // (2,8,8)
    const float* agw      = (const float*)d_in[8];   // (2,64,64)
    const float* agb      = (const float*)d_in[9];   // (2,64)
    const float* rw       = (const float*)d_in[10];  // (2,64,64)
    const float* rb       = (const float*)d_in[11];  // (2,64)

    int E = in_sizes[0] / 3;
    if (E > EMAX) E = EMAX;

    const int TB = 256;
    int ebl = (E + TB - 1) / TB;

    // CSR build (layer-independent)
    zero_deg_kernel<<<(R + TB - 1) / TB, TB>>>();
    hist_kernel<<<ebl, TB>>>(trip, E);
    scan_kernel<<<1, 1024>>>();
    scatter_kernel<<<ebl, TB>>>(trip, E);

    // init: emb = relu(rel_emb @ p1w + p1b)
    gemm_kernel<<<R / 64, 256>>>(rel_emb, p1w, p1b, 0, 1);

    for (int l = 0; l < 2; l++) {
        const float* pwl = apw + (size_t)l * 128 * 64;
        // a_head = emb @ pw[:64]
        gemm_kernel<<<R / 64, 256>>>(nullptr, pwl, nullptr, 1, 0);
        // a_tail = emb @ pw[64:] + pb
        gemm_kernel<<<R / 64, 256>>>(nullptr, pwl + 64 * 64, apb + l * 64, 2, 0);
        // w_tail = emb @ aw + ab
        gemm_kernel<<<R / 64, 256>>>(nullptr, agw + (size_t)l * 4096, agb + l * 64, 3, 0);
        // res = relu(emb @ rw + rb)
        gemm_kernel<<<R / 64, 256>>>(nullptr, rw + (size_t)l * 4096, rb + l * 64, 4, 1);
        // attention + epilogue
        attn_kernel<<<R / 8, 256>>>(abin + l * NBIN * HN, avec + l * HN * 8,
                                    (l == 1) ? (float*)d_out : nullptr);
    }
}

// round 3
// speedup vs baseline: 1.0393x; 1.0393x over previous
#include <cuda_runtime.h>
#include <math.h>

#define R 40000
#define EMAX 500000
#define DH 64
#define NBIN 10
#define HN 8

// ---------------- scratch ----------------
__device__ float g_emb  [R*DH];
__device__ float g_ahead[R*DH];
__device__ float g_attw [R*128];   // interleaved: per col-pair c: [at0,at1,wt0,wt1]
__device__ float g_res  [R*DH];
__device__ int   g_deg  [R];
__device__ int   g_off  [R+1];
__device__ int   g_cursor[R];
__device__ int   g_etb  [EMAX];    // packed: tail | (bin<<20)

__device__ __forceinline__ float lk(float x) { return x > 0.f ? x : 0.2f * x; }

#define FMA2(acc, a, b) asm("fma.rn.f32x2 %0, %1, %2, %0;" : "+l"(acc) : "l"(a), "l"(b))
#define PACK2(d, lo, hi) asm("mov.b64 %0, {%1, %2};" : "=l"(d) : "f"(lo), "f"(hi))
#define UNPK2(lo, hi, s) asm("mov.b64 {%0, %1}, %2;" : "=f"(lo), "=f"(hi) : "l"(s))

// ---------------- CSR build ----------------
__global__ void zero_deg_kernel() {
    int i = blockIdx.x * blockDim.x + threadIdx.x;
    if (i < R) g_deg[i] = 0;
}

__global__ void hist_kernel(const int* __restrict__ trip, int E) {
    int e = blockIdx.x * blockDim.x + threadIdx.x;
    if (e < E) {
        int h = trip[e * 3];
        h = min(max(h, 0), R - 1);
        atomicAdd(&g_deg[h], 1);
    }
}

__global__ void scan_kernel() {
    __shared__ int wsum[32];
    int t = threadIdx.x;
    int lane = t & 31, wid = t >> 5;
    if (t == 0) g_off[0] = 0;
    int carry = 0;
    for (int base = 0; base < R; base += 1024) {
        int idx = base + t;
        int v = (idx < R) ? g_deg[idx] : 0;
        int iv = v;
        #pragma unroll
        for (int o = 1; o < 32; o <<= 1) {
            int n = __shfl_up_sync(0xffffffffu, iv, o);
            if (lane >= o) iv += n;
        }
        if (lane == 31) wsum[wid] = iv;
        __syncthreads();
        if (wid == 0) {
            int ws = wsum[lane];
            #pragma unroll
            for (int o = 1; o < 32; o <<= 1) {
                int n = __shfl_up_sync(0xffffffffu, ws, o);
                if (lane >= o) ws += n;
            }
            wsum[lane] = ws;
        }
        __syncthreads();
        int prev = (wid > 0) ? wsum[wid - 1] : 0;
        int inc = carry + prev + iv;
        if (idx < R) { g_off[idx + 1] = inc; g_cursor[idx] = inc - v; }
        int total = wsum[31];
        __syncthreads();
        carry += total;
    }
}

__global__ void scatter_kernel(const int* __restrict__ trip, int E) {
    int e = blockIdx.x * blockDim.x + threadIdx.x;
    if (e < E) {
        int h = trip[e * 3];
        int t = trip[e * 3 + 1];
        int b = trip[e * 3 + 2];
        h = min(max(h, 0), R - 1);
        t = min(max(t, 0), R - 1);
        b = min(max(b, 0), NBIN - 1);
        int p = atomicAdd(&g_cursor[h], 1);
        g_etb[p] = t | (b << 20);
    }
}

// ---------------- init GEMM: g_emb = relu(X @ W + b) ----------------
__global__ void gemm1_kernel(const float* __restrict__ X, const float* __restrict__ W,
                             const float* __restrict__ bias) {
    __shared__ float sW[64 * 64];
    __shared__ float sX[64 * 65];
    int t = threadIdx.x;
    const float* Xb = X + (size_t)blockIdx.x * 4096;
    #pragma unroll
    for (int i = 0; i < 16; i++) {
        int idx = t + i * 256;
        sW[idx] = W[idx];
        sX[(idx >> 6) * 65 + (idx & 63)] = Xb[idx];
    }
    __syncthreads();
    int cg = (t & 15) * 4;
    int rb = (t >> 4) * 4;
    unsigned long long acc[4][2] = {};
    const float* x0 = &sX[rb * 65];
    #pragma unroll 8
    for (int k = 0; k < 64; k++) {
        const ulonglong2 w = *(const ulonglong2*)&sW[k * 64 + cg];
        #pragma unroll
        for (int r = 0; r < 4; r++) {
            float xv = x0[r * 65 + k];
            unsigned long long xp; PACK2(xp, xv, xv);
            FMA2(acc[r][0], xp, w.x);
            FMA2(acc[r][1], xp, w.y);
        }
    }
    float4 b4 = *(const float4*)&bias[cg];
    int row = blockIdx.x * 64 + rb;
    #pragma unroll
    for (int r = 0; r < 4; r++) {
        float v0, v1, v2, v3;
        UNPK2(v0, v1, acc[r][0]);
        UNPK2(v2, v3, acc[r][1]);
        float4 o;
        o.x = fmaxf(v0 + b4.x, 0.f);
        o.y = fmaxf(v1 + b4.y, 0.f);
        o.z = fmaxf(v2 + b4.z, 0.f);
        o.w = fmaxf(v3 + b4.w, 0.f);
        *(float4*)&g_emb[(row + r) * 64 + cg] = o;
    }
}

// ---------------- fused 4-matrix GEMM per layer --------------------
// pass0: m0 = emb@pw_head -> g_ahead ; m1 = emb@pw_tail + pb -> attw[.. +0,1]
// pass1: m0 = emb@aw + ab -> attw[.. +2,3] ; m1 = relu(emb@rw + rb) -> g_res
__device__ __forceinline__ void mma_pass(const float* sW, const float* sX,
                                         int cg, int rb,
                                         unsigned long long acc[2][4][2]) {
    const float* x0 = &sX[rb * 64];
    #pragma unroll 8
    for (int k = 0; k < 64; k++) {
        const ulonglong2 w0 = *(const ulonglong2*)&sW[k * 64 + cg];
        const ulonglong2 w1 = *(const ulonglong2*)&sW[4096 + k * 64 + cg];
        #pragma unroll
        for (int r = 0; r < 4; r++) {
            float xv = x0[r * 64 + k];
            unsigned long long xp; PACK2(xp, xv, xv);
            FMA2(acc[0][r][0], xp, w0.x);
            FMA2(acc[0][r][1], xp, w0.y);
            FMA2(acc[1][r][0], xp, w1.x);
            FMA2(acc[1][r][1], xp, w1.y);
        }
    }
}

__global__ __launch_bounds__(256) void gemm4_kernel(
    const float* __restrict__ PW,    // 128x64 (head part then tail part)
    const float* __restrict__ AW,    // 64x64 aggr
    const float* __restrict__ RW,    // 64x64 res
    const float* __restrict__ pb,
    const float* __restrict__ ab,
    const float* __restrict__ rbv) {
    __shared__ float sW[2 * 4096];   // 32KB
    __shared__ float sX[4096];       // 16KB  (total 48KB exactly)
    int t = threadIdx.x;
    const float* Xb = g_emb + (size_t)blockIdx.x * 4096;
    #pragma unroll
    for (int i = 0; i < 16; i++) {
        int idx = t + i * 256;
        sX[idx] = Xb[idx];
        sW[idx] = PW[idx];              // first 4096 of PW (head)
        sW[idx + 4096] = PW[idx + 4096]; // tail half
    }
    __syncthreads();

    int cg = (t & 15) * 4;
    int rb = (t >> 4) * 4;
    int row0 = blockIdx.x * 64 + rb;

    // ---- pass 0: ahead + atail ----
    {
        unsigned long long acc[2][4][2] = {};
        mma_pass(sW, sX, cg, rb, acc);
        float4 bt = *(const float4*)&pb[cg];
        #pragma unroll
        for (int r = 0; r < 4; r++) {
            int row = row0 + r;
            float v0, v1, v2, v3;
            UNPK2(v0, v1, acc[0][r][0]);
            UNPK2(v2, v3, acc[0][r][1]);
            *(float4*)&g_ahead[row * 64 + cg] = make_float4(v0, v1, v2, v3);
            UNPK2(v0, v1, acc[1][r][0]);
            UNPK2(v2, v3, acc[1][r][1]);
            *(float2*)&g_attw[row * 128 + cg * 2]     = make_float2(v0 + bt.x, v1 + bt.y);
            *(float2*)&g_attw[row * 128 + cg * 2 + 4] = make_float2(v2 + bt.z, v3 + bt.w);
        }
    }
    __syncthreads();
    // reload weights for pass 1
    #pragma unroll
    for (int i = 0; i < 16; i++) {
        int idx = t + i * 256;
        sW[idx] = AW[idx];
        sW[idx + 4096] = RW[idx];
    }
    __syncthreads();
    // ---- pass 1: wtail + res ----
    {
        unsigned long long acc[2][4][2] = {};
        mma_pass(sW, sX, cg, rb, acc);
        float4 ba = *(const float4*)&ab[cg];
        float4 br = *(const float4*)&rbv[cg];
        #pragma unroll
        for (int r = 0; r < 4; r++) {
            int row = row0 + r;
            float v0, v1, v2, v3;
            UNPK2(v0, v1, acc[0][r][0]);
            UNPK2(v2, v3, acc[0][r][1]);
            *(float2*)&g_attw[row * 128 + cg * 2 + 2] = make_float2(v0 + ba.x, v1 + ba.y);
            *(float2*)&g_attw[row * 128 + cg * 2 + 6] = make_float2(v2 + ba.z, v3 + ba.w);
            UNPK2(v0, v1, acc[1][r][0]);
            UNPK2(v2, v3, acc[1][r][1]);
            float4 o;
            o.x = fmaxf(v0 + br.x, 0.f);
            o.y = fmaxf(v1 + br.y, 0.f);
            o.z = fmaxf(v2 + br.z, 0.f);
            o.w = fmaxf(v3 + br.w, 0.f);
            *(float4*)&g_res[row * 64 + cg] = o;
        }
    }
}

// ---------------- attention: one warp per node, online softmax --------------
__global__ void attn_kernel(const float* __restrict__ abin,
                            const float* __restrict__ avec,
                            float* outp) {
    __shared__ float s_abin[NBIN * HN];
    int t = threadIdx.x;
    if (t < NBIN * HN) s_abin[t] = lk(abin[t]);
    __syncthreads();

    int warp = t >> 5, lane = t & 31;
    int r = blockIdx.x * 8 + warp;
    if (r >= R) return;

    int h = lane >> 2;
    float2 ahv = ((const float2*)g_ahead)[r * 32 + lane];
    float avx = avec[h * 8 + (lane & 3) * 2];
    float avy = avec[h * 8 + (lane & 3) * 2 + 1];
    const float4* AWp = (const float4*)g_attw;

    float m = -INFINITY, s = 0.f, a0 = 0.f, a1 = 0.f;
    int i = g_off[r], end = g_off[r + 1];

    if (i < end) {
        int etb = g_etb[i];
        float4 cur = AWp[(size_t)(etb & 0xFFFFF) * 32 + lane];
        int bb = etb >> 20;
        for (;;) {
            int inext = i + 1;
            int etb2 = 0; float4 nxt = make_float4(0.f, 0.f, 0.f, 0.f);
            bool more = inext < end;
            if (more) {
                etb2 = g_etb[inext];
                nxt = AWp[(size_t)(etb2 & 0xFFFFF) * 32 + lane];
            }
            float z0 = lk(ahv.x + cur.x);
            float z1 = lk(ahv.y + cur.y);
            float p = z0 * avx + z1 * avy;
            p += __shfl_xor_sync(0xffffffffu, p, 1);
            p += __shfl_xor_sync(0xffffffffu, p, 2);
            float raw = p + s_abin[bb * 8 + h];
            float mn = fmaxf(m, raw);
            float sc = __expf(m - mn);
            float e  = __expf(raw - mn);
            s  = s  * sc + e;
            a0 = a0 * sc + e * cur.z;
            a1 = a1 * sc + e * cur.w;
            m = mn;
            if (!more) break;
            i = inext;
            cur = nxt;
            bb = etb2 >> 20;
        }
    }
    float inv = 1.f / (s + 1e-16f);
    float o0 = fmaxf(a0 * inv, 0.f);
    float o1 = fmaxf(a1 * inv, 0.f);
    float2 rv = ((const float2*)g_res)[r * 32 + lane];
    float2 ov;
    ov.x = o0 + rv.x;
    ov.y = o1 + rv.y;
    float* Y = outp ? outp : g_emb;
    ((float2*)Y)[r * 32 + lane] = ov;
}

// ---------------- host ----------------
extern "C" void kernel_launch(void* const* d_in, const int* in_sizes, int n_in,
                              void* d_out, int out_size) {
    const int*   trip     = (const int*)d_in[0];     // int32 triplets
    const float* rel_emb  = (const float*)d_in[1];
    const float* p1w      = (const float*)d_in[2];
    const float* p1b      = (const float*)d_in[3];
    const float* apw      = (const float*)d_in[4];   // (2,128,64)
    const float* apb      = (const float*)d_in[5];   // (2,64)
    const float* abin     = (const float*)d_in[6];   // (2,10,8,1)
    const float* avec     = (const float*)d_in[7];   // (2,8,8)
    const float* agw      = (const float*)d_in[8];   // (2,64,64)
    const float* agb      = (const float*)d_in[9];   // (2,64)
    const float* rw       = (const float*)d_in[10];  // (2,64,64)
    const float* rb       = (const float*)d_in[11];  // (2,64)

    int E = in_sizes[0] / 3;
    if (E > EMAX) E = EMAX;

    const int TB = 256;
    int ebl = (E + TB - 1) / TB;

    zero_deg_kernel<<<(R + TB - 1) / TB, TB>>>();
    hist_kernel<<<ebl, TB>>>(trip, E);
    scan_kernel<<<1, 1024>>>();
    scatter_kernel<<<ebl, TB>>>(trip, E);

    gemm1_kernel<<<R / 64, 256>>>(rel_emb, p1w, p1b);

    for (int l = 0; l < 2; l++) {
        gemm4_kernel<<<R / 64, 256>>>(apw + (size_t)l * 8192,
                                      agw + (size_t)l * 4096,
                                      rw  + (size_t)l * 4096,
                                      apb + l * 64,
                                      agb + l * 64,
                                      rb  + l * 64);
        attn_kernel<<<R / 8, 256>>>(abin + l * NBIN * HN, avec + l * HN * 8,
                                    (l == 1) ? (float*)d_out : nullptr);
    }
}

// round 4
// speedup vs baseline: 1.1682x; 1.1240x over previous
#include <cuda_runtime.h>
#include <math.h>

#define R 40000
#define EMAX 500000
#define DH 64
#define NBIN 10
#define HN 8
#define NSB 40   // scan blocks: ceil(40000/1024)

// ---------------- scratch ----------------
__device__ float g_emb  [R*DH];
__device__ float g_ahead[R*DH];
__device__ float g_attw [R*128];   // interleaved per col-pair: [at0,at1,wt0,wt1]
__device__ float g_res  [R*DH];
__device__ int   g_deg  [R];
__device__ int   g_off  [R+1];
__device__ int   g_cursor[R];
__device__ int   g_bsum [NSB];
__device__ int   g_bpre [NSB];
__device__ int   g_etb  [EMAX];    // packed: tail | (bin<<20)

__device__ __forceinline__ float lk(float x) { return x > 0.f ? x : 0.2f * x; }

#define FMA2(acc, a, b) asm("fma.rn.f32x2 %0, %1, %2, %0;" : "+l"(acc) : "l"(a), "l"(b))
#define PACK2(d, lo, hi) asm("mov.b64 %0, {%1, %2};" : "=l"(d) : "f"(lo), "f"(hi))
#define UNPK2(lo, hi, s) asm("mov.b64 {%0, %1}, %2;" : "=f"(lo), "=f"(hi) : "l"(s))

// ---------------- CSR build ----------------
__global__ void zero_deg_kernel() {
    int i = blockIdx.x * blockDim.x + threadIdx.x;
    if (i < R) g_deg[i] = 0;
}

__global__ void hist_kernel(const int* __restrict__ trip, int E) {
    int e = blockIdx.x * blockDim.x + threadIdx.x;
    if (e < E) {
        int h = trip[e * 3];
        h = min(max(h, 0), R - 1);
        atomicAdd(&g_deg[h], 1);
    }
}

// phase 1: each block scans 1024 degs, writes local inclusive to g_off[i+1], total to g_bsum
__global__ void scan1_kernel() {
    __shared__ int ws[8];
    int t = threadIdx.x;
    int lane = t & 31, wid = t >> 5;
    int base = blockIdx.x * 1024 + t * 4;
    int v0 = (base + 0 < R) ? g_deg[base + 0] : 0;
    int v1 = (base + 1 < R) ? g_deg[base + 1] : 0;
    int v2 = (base + 2 < R) ? g_deg[base + 2] : 0;
    int v3 = (base + 3 < R) ? g_deg[base + 3] : 0;
    v1 += v0; v2 += v1; v3 += v2;
    int tot = v3;
    int sc = tot;
    #pragma unroll
    for (int o = 1; o < 32; o <<= 1) {
        int n = __shfl_up_sync(0xffffffffu, sc, o);
        if (lane >= o) sc += n;
    }
    if (lane == 31) ws[wid] = sc;
    __syncthreads();
    if (wid == 0) {
        int x = (lane < 8) ? ws[lane] : 0;
        #pragma unroll
        for (int o = 1; o < 8; o <<= 1) {
            int n = __shfl_up_sync(0xffffffffu, x, o);
            if (lane >= o) x += n;
        }
        if (lane < 8) ws[lane] = x;
    }
    __syncthreads();
    int pre = sc - tot + (wid ? ws[wid - 1] : 0);  // exclusive prefix of this thread
    if (base + 0 < R) g_off[base + 1] = pre + v0;
    if (base + 1 < R) g_off[base + 2] = pre + v1;
    if (base + 2 < R) g_off[base + 3] = pre + v2;
    if (base + 3 < R) g_off[base + 4] = pre + v3;
    if (t == 255) g_bsum[blockIdx.x] = pre + tot;
}

// phase 2: one warp scans NSB block sums -> exclusive prefixes
__global__ void scan2_kernel() {
    int lane = threadIdx.x;
    int carry = 0;
    for (int base = 0; base < NSB; base += 32) {
        int v = (base + lane < NSB) ? g_bsum[base + lane] : 0;
        int sc = v;
        #pragma unroll
        for (int o = 1; o < 32; o <<= 1) {
            int n = __shfl_up_sync(0xffffffffu, sc, o);
            if (lane >= o) sc += n;
        }
        if (base + lane < NSB) g_bpre[base + lane] = carry + sc - v;
        carry += __shfl_sync(0xffffffffu, sc, 31);
    }
    if (lane == 0) g_off[0] = 0;
}

// phase 3: add block prefixes, derive cursors
__global__ void scan3_kernel() {
    int i = blockIdx.x * blockDim.x + threadIdx.x;
    if (i < R) {
        int off = g_off[i + 1] + g_bpre[i >> 10];
        g_off[i + 1] = off;
        g_cursor[i] = off - g_deg[i];
    }
}

__global__ void scatter_kernel(const int* __restrict__ trip, int E) {
    int e = blockIdx.x * blockDim.x + threadIdx.x;
    if (e < E) {
        int h = trip[e * 3];
        int t = trip[e * 3 + 1];
        int b = trip[e * 3 + 2];
        h = min(max(h, 0), R - 1);
        t = min(max(t, 0), R - 1);
        b = min(max(b, 0), NBIN - 1);
        int p = atomicAdd(&g_cursor[h], 1);
        g_etb[p] = t | (b << 20);
    }
}

// ---------------- init GEMM: g_emb = relu(X @ W + b) ----------------
__global__ void gemm1_kernel(const float* __restrict__ X, const float* __restrict__ W,
                             const float* __restrict__ bias) {
    __shared__ float sW[4096];
    __shared__ float sX[4096];
    int t = threadIdx.x;
    const float4* Xb4 = (const float4*)(X + (size_t)blockIdx.x * 4096);
    const float4* W4  = (const float4*)W;
    float4* sX4 = (float4*)sX;
    float4* sW4 = (float4*)sW;
    #pragma unroll
    for (int i = 0; i < 4; i++) {
        int id = t + i * 256;
        sX4[id] = Xb4[id];
        sW4[id] = W4[id];
    }
    __syncthreads();
    int cg = (t & 15) * 4;
    int rb = (t >> 4) * 4;
    unsigned long long acc[4][2] = {};
    const float* x0 = &sX[rb * 64];
    #pragma unroll 8
    for (int k = 0; k < 64; k++) {
        const ulonglong2 w = *(const ulonglong2*)&sW[k * 64 + cg];
        #pragma unroll
        for (int r = 0; r < 4; r++) {
            float xv = x0[r * 64 + k];
            unsigned long long xp; PACK2(xp, xv, xv);
            FMA2(acc[r][0], xp, w.x);
            FMA2(acc[r][1], xp, w.y);
        }
    }
    float4 b4 = *(const float4*)&bias[cg];
    int row = blockIdx.x * 64 + rb;
    #pragma unroll
    for (int r = 0; r < 4; r++) {
        float v0, v1, v2, v3;
        UNPK2(v0, v1, acc[r][0]);
        UNPK2(v2, v3, acc[r][1]);
        float4 o;
        o.x = fmaxf(v0 + b4.x, 0.f);
        o.y = fmaxf(v1 + b4.y, 0.f);
        o.z = fmaxf(v2 + b4.z, 0.f);
        o.w = fmaxf(v3 + b4.w, 0.f);
        *(float4*)&g_emb[(row + r) * 64 + cg] = o;
    }
}

// ---------------- fused 4-matrix GEMM per layer --------------------
__device__ __forceinline__ void mma_pass(const float* sW, const float* sX,
                                         int cg, int rb,
                                         unsigned long long acc[2][4][2]) {
    const float* x0 = &sX[rb * 64];
    #pragma unroll 8
    for (int k = 0; k < 64; k++) {
        const ulonglong2 w0 = *(const ulonglong2*)&sW[k * 64 + cg];
        const ulonglong2 w1 = *(const ulonglong2*)&sW[4096 + k * 64 + cg];
        #pragma unroll
        for (int r = 0; r < 4; r++) {
            float xv = x0[r * 64 + k];
            unsigned long long xp; PACK2(xp, xv, xv);
            FMA2(acc[0][r][0], xp, w0.x);
            FMA2(acc[0][r][1], xp, w0.y);
            FMA2(acc[1][r][0], xp, w1.x);
            FMA2(acc[1][r][1], xp, w1.y);
        }
    }
}

__global__ __launch_bounds__(256) void gemm4_kernel(
    const float* __restrict__ PW,    // 128x64
    const float* __restrict__ AW,    // 64x64
    const float* __restrict__ RW,    // 64x64
    const float* __restrict__ pb,
    const float* __restrict__ ab,
    const float* __restrict__ rbv) {
    __shared__ float sW[2 * 4096];   // 32KB
    __shared__ float sX[4096];       // 16KB
    int t = threadIdx.x;
    const float4* Xb4 = (const float4*)(g_emb + (size_t)blockIdx.x * 4096);
    const float4* PW4 = (const float4*)PW;
    float4* sX4 = (float4*)sX;
    float4* sW4 = (float4*)sW;
    #pragma unroll
    for (int i = 0; i < 4; i++) {
        int id = t + i * 256;
        sX4[id] = Xb4[id];
        sW4[id] = PW4[id];
        sW4[id + 1024] = PW4[id + 1024];
    }
    __syncthreads();

    int cg = (t & 15) * 4;
    int rb = (t >> 4) * 4;
    int row0 = blockIdx.x * 64 + rb;

    // ---- pass 0: ahead + atail ----
    {
        unsigned long long acc[2][4][2] = {};
        mma_pass(sW, sX, cg, rb, acc);
        float4 bt = *(const float4*)&pb[cg];
        #pragma unroll
        for (int r = 0; r < 4; r++) {
            int row = row0 + r;
            float v0, v1, v2, v3;
            UNPK2(v0, v1, acc[0][r][0]);
            UNPK2(v2, v3, acc[0][r][1]);
            *(float4*)&g_ahead[row * 64 + cg] = make_float4(v0, v1, v2, v3);
            UNPK2(v0, v1, acc[1][r][0]);
            UNPK2(v2, v3, acc[1][r][1]);
            *(float2*)&g_attw[row * 128 + cg * 2]     = make_float2(v0 + bt.x, v1 + bt.y);
            *(float2*)&g_attw[row * 128 + cg * 2 + 4] = make_float2(v2 + bt.z, v3 + bt.w);
        }
    }
    __syncthreads();
    const float4* AW4 = (const float4*)AW;
    const float4* RW4 = (const float4*)RW;
    #pragma unroll
    for (int i = 0; i < 4; i++) {
        int id = t + i * 256;
        sW4[id] = AW4[id];
        sW4[id + 1024] = RW4[id];
    }
    __syncthreads();
    // ---- pass 1: wtail + res ----
    {
        unsigned long long acc[2][4][2] = {};
        mma_pass(sW, sX, cg, rb, acc);
        float4 ba = *(const float4*)&ab[cg];
        float4 br = *(const float4*)&rbv[cg];
        #pragma unroll
        for (int r = 0; r < 4; r++) {
            int row = row0 + r;
            float v0, v1, v2, v3;
            UNPK2(v0, v1, acc[0][r][0]);
            UNPK2(v2, v3, acc[0][r][1]);
            *(float2*)&g_attw[row * 128 + cg * 2 + 2] = make_float2(v0 + ba.x, v1 + ba.y);
            *(float2*)&g_attw[row * 128 + cg * 2 + 6] = make_float2(v2 + ba.z, v3 + ba.w);
            UNPK2(v0, v1, acc[1][r][0]);
            UNPK2(v2, v3, acc[1][r][1]);
            float4 o;
            o.x = fmaxf(v0 + br.x, 0.f);
            o.y = fmaxf(v1 + br.y, 0.f);
            o.z = fmaxf(v2 + br.z, 0.f);
            o.w = fmaxf(v3 + br.w, 0.f);
            *(float4*)&g_res[row * 64 + cg] = o;
        }
    }
}

// ---------------- attention: one warp per node, online softmax --------------
__global__ void attn_kernel(const float* __restrict__ abin,
                            const float* __restrict__ avec,
                            float* outp) {
    __shared__ float s_abin[NBIN * HN];
    int t = threadIdx.x;
    if (t < NBIN * HN) s_abin[t] = lk(abin[t]);
    __syncthreads();

    int warp = t >> 5, lane = t & 31;
    int r = blockIdx.x * 8 + warp;
    if (r >= R) return;

    int h = lane >> 2;
    float2 ahv = ((const float2*)g_ahead)[r * 32 + lane];
    float avx = avec[h * 8 + (lane & 3) * 2];
    float avy = avec[h * 8 + (lane & 3) * 2 + 1];
    const float4* AWp = (const float4*)g_attw;

    float m = -INFINITY, s = 0.f, a0 = 0.f, a1 = 0.f;
    int i = g_off[r], end = g_off[r + 1];

    if (i < end) {
        int etb = g_etb[i];
        float4 cur = AWp[(etb & 0xFFFFF) * 32 + lane];
        int bb = etb >> 20;
        for (;;) {
            int inext = i + 1;
            int etb2 = 0; float4 nxt = make_float4(0.f, 0.f, 0.f, 0.f);
            bool more = inext < end;
            if (more) {
                etb2 = g_etb[inext];
                nxt = AWp[(etb2 & 0xFFFFF) * 32 + lane];
            }
            float z0 = lk(ahv.x + cur.x);
            float z1 = lk(ahv.y + cur.y);
            float p = z0 * avx + z1 * avy;
            p += __shfl_xor_sync(0xffffffffu, p, 1);
            p += __shfl_xor_sync(0xffffffffu, p, 2);
            float raw = p + s_abin[bb * 8 + h];
            float mn = fmaxf(m, raw);
            float sc = __expf(m - mn);
            float e  = __expf(raw - mn);
            s  = s  * sc + e;
            a0 = a0 * sc + e * cur.z;
            a1 = a1 * sc + e * cur.w;
            m = mn;
            if (!more) break;
            i = inext;
            cur = nxt;
            bb = etb2 >> 20;
        }
    }
    float inv = 1.f / (s + 1e-16f);
    float o0 = fmaxf(a0 * inv, 0.f);
    float o1 = fmaxf(a1 * inv, 0.f);
    float2 rv = ((const float2*)g_res)[r * 32 + lane];
    float2 ov;
    ov.x = o0 + rv.x;
    ov.y = o1 + rv.y;
    float* Y = outp ? outp : g_emb;
    ((float2*)Y)[r * 32 + lane] = ov;
}

// ---------------- host ----------------
extern "C" void kernel_launch(void* const* d_in, const int* in_sizes, int n_in,
                              void* d_out, int out_size) {
    const int*   trip     = (const int*)d_in[0];
    const float* rel_emb  = (const float*)d_in[1];
    const float* p1w      = (const float*)d_in[2];
    const float* p1b      = (const float*)d_in[3];
    const float* apw      = (const float*)d_in[4];
    const float* apb      = (const float*)d_in[5];
    const float* abin     = (const float*)d_in[6];
    const float* avec     = (const float*)d_in[7];
    const float* agw      = (const float*)d_in[8];
    const float* agb      = (const float*)d_in[9];
    const float* rw       = (const float*)d_in[10];
    const float* rb       = (const float*)d_in[11];

    int E = in_sizes[0] / 3;
    if (E > EMAX) E = EMAX;

    const int TB = 256;
    int ebl = (E + TB - 1) / TB;

    zero_deg_kernel<<<(R + TB - 1) / TB, TB>>>();
    hist_kernel<<<ebl, TB>>>(trip, E);
    scan1_kernel<<<NSB, 256>>>();
    scan2_kernel<<<1, 32>>>();
    scan3_kernel<<<(R + TB - 1) / TB, TB>>>();
    scatter_kernel<<<ebl, TB>>>(trip, E);

    gemm1_kernel<<<R / 64, 256>>>(rel_emb, p1w, p1b);

    for (int l = 0; l < 2; l++) {
        gemm4_kernel<<<R / 64, 256>>>(apw + (size_t)l * 8192,
                                      agw + (size_t)l * 4096,
                                      rw  + (size_t)l * 4096,
                                      apb + l * 64,
                                      agb + l * 64,
                                      rb  + l * 64);
        attn_kernel<<<R / 8, 256>>>(abin + l * NBIN * HN, avec + l * HN * 8,
                                    (l == 1) ? (float*)d_out : nullptr);
    }
}

// round 5
// speedup vs baseline: 1.2538x; 1.0733x over previous
#include <cuda_runtime.h>
#include <cuda_fp16.h>
#include <math.h>

#define R 40000
#define EMAX 500000
#define DH 64
#define NBIN 10
#define HN 8
#define NSB 40   // scan blocks: ceil(40000/1024)

// ---------------- scratch ----------------
__device__ float  g_emb  [R*DH];
__device__ float  g_ahead[R*DH];
__device__ __half g_attwh[R*128];  // per lane l: [at(2l),at(2l+1),wt(2l),wt(2l+1)] as 2x half2
__device__ float  g_res  [R*DH];
__device__ int    g_deg  [R];
__device__ int    g_off  [R+1];
__device__ int    g_cursor[R];
__device__ int    g_pub  [NSB];    // lookback publish: aggregate+1 (0 = not ready)
__device__ int    g_etb  [EMAX];   // packed: tail | (bin<<20)

__device__ __forceinline__ float lk(float x) { return x > 0.f ? x : 0.2f * x; }

#define FMA2(acc, a, b) asm("fma.rn.f32x2 %0, %1, %2, %0;" : "+l"(acc) : "l"(a), "l"(b))
#define PACK2(d, lo, hi) asm("mov.b64 %0, {%1, %2};" : "=l"(d) : "f"(lo), "f"(hi))
#define UNPK2(lo, hi, s) asm("mov.b64 {%0, %1}, %2;" : "=f"(lo), "=f"(hi) : "l"(s))

// ---------------- CSR build ----------------
__global__ void zero_kernel() {
    int i = blockIdx.x * blockDim.x + threadIdx.x;
    if (i < R) g_deg[i] = 0;
    if (i < NSB) g_pub[i] = 0;
}

__global__ void hist_kernel(const int* __restrict__ trip, int E) {
    int e = blockIdx.x * blockDim.x + threadIdx.x;
    if (e < E) {
        int h = trip[e * 3];
        h = min(max(h, 0), R - 1);
        atomicAdd(&g_deg[h], 1);
    }
}

// fused single-pass scan with decoupled lookback (40 blocks, all co-resident)
__global__ void scan_kernel() {
    __shared__ int ws[8];
    __shared__ int s_bp;
    int t = threadIdx.x;
    int lane = t & 31, wid = t >> 5, b = blockIdx.x;
    int base = b * 1024 + t * 4;

    int d0 = (base + 0 < R) ? g_deg[base + 0] : 0;
    int d1 = (base + 1 < R) ? g_deg[base + 1] : 0;
    int d2 = (base + 2 < R) ? g_deg[base + 2] : 0;
    int d3 = (base + 3 < R) ? g_deg[base + 3] : 0;
    int v1 = d0 + d1, v2 = v1 + d2, v3 = v2 + d3;
    int tot = v3;
    int sc = tot;
    #pragma unroll
    for (int o = 1; o < 32; o <<= 1) {
        int n = __shfl_up_sync(0xffffffffu, sc, o);
        if (lane >= o) sc += n;
    }
    if (lane == 31) ws[wid] = sc;
    __syncthreads();
    if (wid == 0) {
        int x = (lane < 8) ? ws[lane] : 0;
        #pragma unroll
        for (int o = 1; o < 8; o <<= 1) {
            int n = __shfl_up_sync(0xffffffffu, x, o);
            if (lane >= o) x += n;
        }
        if (lane < 8) ws[lane] = x;
    }
    __syncthreads();
    int pre = sc - tot + (wid ? ws[wid - 1] : 0);   // thread exclusive prefix in block

    // publish block aggregate (+1 so 0 means "not ready"; single-word = no fence race)
    if (t == 0) atomicExch(&g_pub[b], ws[7] + 1);

    // lookback: warp 0 sums all predecessor aggregates
    if (wid == 0) {
        int sum = 0;
        for (int j = lane; j < b; j += 32) {
            int v;
            do { v = atomicAdd(&g_pub[j], 0); } while (v == 0);
            sum += v - 1;
        }
        #pragma unroll
        for (int o = 16; o > 0; o >>= 1) sum += __shfl_xor_sync(0xffffffffu, sum, o);
        if (lane == 0) s_bp = sum;
    }
    __syncthreads();
    int p = s_bp + pre;   // global exclusive prefix for this thread's 4 elems

    if (base + 0 < R) { g_off[base + 1] = p + d0; g_cursor[base + 0] = p; }
    if (base + 1 < R) { g_off[base + 2] = p + v1; g_cursor[base + 1] = p + d0; }
    if (base + 2 < R) { g_off[base + 3] = p + v2; g_cursor[base + 2] = p + v1; }
    if (base + 3 < R) { g_off[base + 4] = p + v3; g_cursor[base + 3] = p + v2; }
    if (b == 0 && t == 0) g_off[0] = 0;
}

__global__ void scatter_kernel(const int* __restrict__ trip, int E) {
    int e = blockIdx.x * blockDim.x + threadIdx.x;
    if (e < E) {
        int h = trip[e * 3];
        int t = trip[e * 3 + 1];
        int b = trip[e * 3 + 2];
        h = min(max(h, 0), R - 1);
        t = min(max(t, 0), R - 1);
        b = min(max(b, 0), NBIN - 1);
        int p = atomicAdd(&g_cursor[h], 1);
        g_etb[p] = t | (b << 20);
    }
}

// ---------------- init GEMM: g_emb = relu(X @ W + b) ----------------
__global__ void gemm1_kernel(const float* __restrict__ X, const float* __restrict__ W,
                             const float* __restrict__ bias) {
    __shared__ float sW[4096];
    __shared__ float sX[4096];
    int t = threadIdx.x;
    const float4* Xb4 = (const float4*)(X + (size_t)blockIdx.x * 4096);
    const float4* W4  = (const float4*)W;
    float4* sX4 = (float4*)sX;
    float4* sW4 = (float4*)sW;
    #pragma unroll
    for (int i = 0; i < 4; i++) {
        int id = t + i * 256;
        sX4[id] = Xb4[id];
        sW4[id] = W4[id];
    }
    __syncthreads();
    int cg = (t & 15) * 4;
    int rb = (t >> 4) * 4;
    unsigned long long acc[4][2] = {};
    const float* x0 = &sX[rb * 64];
    #pragma unroll 8
    for (int k = 0; k < 64; k++) {
        const ulonglong2 w = *(const ulonglong2*)&sW[k * 64 + cg];
        #pragma unroll
        for (int r = 0; r < 4; r++) {
            float xv = x0[r * 64 + k];
            unsigned long long xp; PACK2(xp, xv, xv);
            FMA2(acc[r][0], xp, w.x);
            FMA2(acc[r][1], xp, w.y);
        }
    }
    float4 b4 = *(const float4*)&bias[cg];
    int row = blockIdx.x * 64 + rb;
    #pragma unroll
    for (int r = 0; r < 4; r++) {
        float v0, v1, v2, v3;
        UNPK2(v0, v1, acc[r][0]);
        UNPK2(v2, v3, acc[r][1]);
        float4 o;
        o.x = fmaxf(v0 + b4.x, 0.f);
        o.y = fmaxf(v1 + b4.y, 0.f);
        o.z = fmaxf(v2 + b4.z, 0.f);
        o.w = fmaxf(v3 + b4.w, 0.f);
        *(float4*)&g_emb[(row + r) * 64 + cg] = o;
    }
}

// ---------------- fused 4-matrix GEMM per layer --------------------
__device__ __forceinline__ void mma_pass(const float* sW, const float* sX,
                                         int cg, int rb,
                                         unsigned long long acc[2][4][2]) {
    const float* x0 = &sX[rb * 64];
    #pragma unroll 8
    for (int k = 0; k < 64; k++) {
        const ulonglong2 w0 = *(const ulonglong2*)&sW[k * 64 + cg];
        const ulonglong2 w1 = *(const ulonglong2*)&sW[4096 + k * 64 + cg];
        #pragma unroll
        for (int r = 0; r < 4; r++) {
            float xv = x0[r * 64 + k];
            unsigned long long xp; PACK2(xp, xv, xv);
            FMA2(acc[0][r][0], xp, w0.x);
            FMA2(acc[0][r][1], xp, w0.y);
            FMA2(acc[1][r][0], xp, w1.x);
            FMA2(acc[1][r][1], xp, w1.y);
        }
    }
}

__global__ __launch_bounds__(256) void gemm4_kernel(
    const float* __restrict__ PW,    // 128x64
    const float* __restrict__ AW,    // 64x64
    const float* __restrict__ RW,    // 64x64
    const float* __restrict__ pb,
    const float* __restrict__ ab,
    const float* __restrict__ rbv) {
    __shared__ float sW[2 * 4096];   // 32KB
    __shared__ float sX[4096];       // 16KB
    int t = threadIdx.x;
    const float4* Xb4 = (const float4*)(g_emb + (size_t)blockIdx.x * 4096);
    const float4* PW4 = (const float4*)PW;
    float4* sX4 = (float4*)sX;
    float4* sW4 = (float4*)sW;
    #pragma unroll
    for (int i = 0; i < 4; i++) {
        int id = t + i * 256;
        sX4[id] = Xb4[id];
        sW4[id] = PW4[id];
        sW4[id + 1024] = PW4[id + 1024];
    }
    __syncthreads();

    int cg = (t & 15) * 4;
    int rb = (t >> 4) * 4;
    int row0 = blockIdx.x * 64 + rb;
    __half2* H = (__half2*)g_attwh;   // half2 index: row*64 + lane*2 + slot

    // ---- pass 0: ahead (fp32) + atail (fp16 slot 0) ----
    {
        unsigned long long acc[2][4][2] = {};
        mma_pass(sW, sX, cg, rb, acc);
        float4 bt = *(const float4*)&pb[cg];
        int l0 = cg >> 1;
        #pragma unroll
        for (int r = 0; r < 4; r++) {
            int row = row0 + r;
            float v0, v1, v2, v3;
            UNPK2(v0, v1, acc[0][r][0]);
            UNPK2(v2, v3, acc[0][r][1]);
            *(float4*)&g_ahead[row * 64 + cg] = make_float4(v0, v1, v2, v3);
            UNPK2(v0, v1, acc[1][r][0]);
            UNPK2(v2, v3, acc[1][r][1]);
            H[row * 64 + l0 * 2]       = __floats2half2_rn(v0 + bt.x, v1 + bt.y);
            H[row * 64 + (l0 + 1) * 2] = __floats2half2_rn(v2 + bt.z, v3 + bt.w);
        }
    }
    __syncthreads();
    const float4* AW4 = (const float4*)AW;
    const float4* RW4 = (const float4*)RW;
    #pragma unroll
    for (int i = 0; i < 4; i++) {
        int id = t + i * 256;
        sW4[id] = AW4[id];
        sW4[id + 1024] = RW4[id];
    }
    __syncthreads();
    // ---- pass 1: wtail (fp16 slot 1) + res (fp32) ----
    {
        unsigned long long acc[2][4][2] = {};
        mma_pass(sW, sX, cg, rb, acc);
        float4 ba = *(const float4*)&ab[cg];
        float4 br = *(const float4*)&rbv[cg];
        int l0 = cg >> 1;
        #pragma unroll
        for (int r = 0; r < 4; r++) {
            int row = row0 + r;
            float v0, v1, v2, v3;
            UNPK2(v0, v1, acc[0][r][0]);
            UNPK2(v2, v3, acc[0][r][1]);
            H[row * 64 + l0 * 2 + 1]       = __floats2half2_rn(v0 + ba.x, v1 + ba.y);
            H[row * 64 + (l0 + 1) * 2 + 1] = __floats2half2_rn(v2 + ba.z, v3 + ba.w);
            UNPK2(v0, v1, acc[1][r][0]);
            UNPK2(v2, v3, acc[1][r][1]);
            float4 o;
            o.x = fmaxf(v0 + br.x, 0.f);
            o.y = fmaxf(v1 + br.y, 0.f);
            o.z = fmaxf(v2 + br.z, 0.f);
            o.w = fmaxf(v3 + br.w, 0.f);
            *(float4*)&g_res[row * 64 + cg] = o;
        }
    }
}

// ---------------- attention: one warp per node, online softmax --------------
__global__ void attn_kernel(const float* __restrict__ abin,
                            const float* __restrict__ avec,
                            float* outp) {
    __shared__ float s_abin[NBIN * HN];
    int t = threadIdx.x;
    if (t < NBIN * HN) s_abin[t] = lk(abin[t]);
    __syncthreads();

    int warp = t >> 5, lane = t & 31;
    int r = blockIdx.x * 8 + warp;
    if (r >= R) return;

    int h = lane >> 2;
    float2 ahv = ((const float2*)g_ahead)[r * 32 + lane];
    float avx = avec[h * 8 + (lane & 3) * 2];
    float avy = avec[h * 8 + (lane & 3) * 2 + 1];
    const uint2* AWp = (const uint2*)g_attwh;   // 8B/lane: (at half2, wt half2)

    float m = -INFINITY, s = 0.f, a0 = 0.f, a1 = 0.f;
    int i = g_off[r], end = g_off[r + 1];

    if (i < end) {
        int etb = g_etb[i];
        uint2 cur = AWp[(etb & 0xFFFFF) * 32 + lane];
        int bb = etb >> 20;
        for (;;) {
            int inext = i + 1;
            int etb2 = 0; uint2 nxt = make_uint2(0u, 0u);
            bool more = inext < end;
            if (more) {
                etb2 = g_etb[inext];
                nxt = AWp[(etb2 & 0xFFFFF) * 32 + lane];
            }
            float2 at = __half22float2(*(const __half2*)&cur.x);
            float2 wt = __half22float2(*(const __half2*)&cur.y);
            float z0 = lk(ahv.x + at.x);
            float z1 = lk(ahv.y + at.y);
            float p = z0 * avx + z1 * avy;
            p += __shfl_xor_sync(0xffffffffu, p, 1);
            p += __shfl_xor_sync(0xffffffffu, p, 2);
            float raw = p + s_abin[bb * 8 + h];
            float mn = fmaxf(m, raw);
            float sc = __expf(m - mn);
            float e  = __expf(raw - mn);
            s  = s  * sc + e;
            a0 = a0 * sc + e * wt.x;
            a1 = a1 * sc + e * wt.y;
            m = mn;
            if (!more) break;
            i = inext;
            cur = nxt;
            bb = etb2 >> 20;
        }
    }
    float inv = 1.f / (s + 1e-16f);
    float o0 = fmaxf(a0 * inv, 0.f);
    float o1 = fmaxf(a1 * inv, 0.f);
    float2 rv = ((const float2*)g_res)[r * 32 + lane];
    float2 ov;
    ov.x = o0 + rv.x;
    ov.y = o1 + rv.y;
    float* Y = outp ? outp : g_emb;
    ((float2*)Y)[r * 32 + lane] = ov;
}

// ---------------- host ----------------
extern "C" void kernel_launch(void* const* d_in, const int* in_sizes, int n_in,
                              void* d_out, int out_size) {
    const int*   trip     = (const int*)d_in[0];
    const float* rel_emb  = (const float*)d_in[1];
    const float* p1w      = (const float*)d_in[2];
    const float* p1b      = (const float*)d_in[3];
    const float* apw      = (const float*)d_in[4];
    const float* apb      = (const float*)d_in[5];
    const float* abin     = (const float*)d_in[6];
    const float* avec     = (const float*)d_in[7];
    const float* agw      = (const float*)d_in[8];
    const float* agb      = (const float*)d_in[9];
    const float* rw       = (const float*)d_in[10];
    const float* rb       = (const float*)d_in[11];

    int E = in_sizes[0] / 3;
    if (E > EMAX) E = EMAX;

    const int TB = 256;
    int ebl = (E + TB - 1) / TB;

    zero_kernel<<<(R + TB - 1) / TB, TB>>>();
    hist_kernel<<<ebl, TB>>>(trip, E);
    scan_kernel<<<NSB, 256>>>();
    scatter_kernel<<<ebl, TB>>>(trip, E);

    gemm1_kernel<<<R / 64, 256>>>(rel_emb, p1w, p1b);

    for (int l = 0; l < 2; l++) {
        gemm4_kernel<<<R / 64, 256>>>(apw + (size_t)l * 8192,
                                      agw + (size_t)l * 4096,
                                      rw  + (size_t)l * 4096,
                                      apb + l * 64,
                                      agb + l * 64,
                                      rb  + l * 64);
        attn_kernel<<<R / 8, 256>>>(abin + l * NBIN * HN, avec + l * HN * 8,
                                    (l == 1) ? (float*)d_out : nullptr);
    }
}